// round 5
// baseline (speedup 1.0000x reference)
#include <cuda_runtime.h>
#include <cuda_bf16.h>
#include <math.h>

// Shapes
// x:(16,32,512)  conv1->(16,64,14,254)  conv2->(16,64,14,254)
// concat(128ch) -> 1x1 conv -> (16,64,14,254) -> capsules N=28448, CAPS=8
// ec_w:(N,8,16,8) -> routing 3 iters -> out (16,8)
#define Bsz 16
#define CH 64
#define H1 14
#define W1 254
#define HWp (H1*W1)            // 3556
#define CHWp (CH*HWp)          // 227584
#define Ncap 28448
#define Ecls 8
#define ODv 16

// ---------------- scratch (no malloc allowed) ----------------
__device__ float g_h1[Bsz*CHWp];   // conv1 output (relu) 14.6MB
__device__ float g_y2[Bsz*CHWp];   // conv2 output (relu)
__device__ float g_h3[Bsz*CHWp];   // 1x1 conv output (= u_in flat)
__device__ float g_u [Bsz*Ncap*8]; // capsule-transformed u
__device__ float g_s [3*2048];     // s accumulators per routing iter (B*E*OD = 2048)
__device__ float g_vsum[2048];     // v0 + v1 (+...) running sum

// ---------------- zero small buffers ----------------
__global__ void zero_k() {
    int t = blockIdx.x*256 + threadIdx.x;
    if (t < 3*2048) g_s[t] = 0.f;
    if (t < 2048)   g_vsum[t] = 0.f;
}

// ---------------- conv1: 1->64ch 6x6 stride2, relu ----------------
__global__ void conv1_k(const float* __restrict__ x,
                        const float* __restrict__ w1,
                        const float* __restrict__ b1) {
    __shared__ float xs[6*512];
    __shared__ float ws[2304];
    __shared__ float bs[64];
    int h = blockIdx.x, b = blockIdx.y, t = threadIdx.x;
    const float* xrow = x + b*(32*512) + (2*h)*512;   // rows 2h..2h+5 contiguous
    for (int j = t; j < 3072; j += 256) xs[j] = xrow[j];
    for (int j = t; j < 2304; j += 256) ws[j] = w1[j];
    if (t < 64) bs[t] = b1[t];
    __syncthreads();
    if (t >= W1) return;
    float win[36];
#pragma unroll
    for (int r = 0; r < 6; r++)
#pragma unroll
        for (int k = 0; k < 6; k++) win[r*6+k] = xs[r*512 + 2*t + k];
    float* outp = g_h1 + (size_t)(b*CH*H1 + h)*W1 + t;
    for (int f = 0; f < 64; f++) {
        float a = bs[f];
        const float* wp = ws + f*36;
#pragma unroll
        for (int k = 0; k < 36; k++) a = fmaf(win[k], wp[k], a);
        outp[(size_t)f*HWp] = fmaxf(a, 0.f);
    }
}

// ---------------- conv2: 64->64ch 6x6 stride1, pad(2,3), relu -----
// block = (w-tile of 128, h, b); 128 threads = 8 cout-groups x 16 w-groups
// thread computes 8 couts x 8 w outputs. cin tiled by 8 through smem.
#define C2_SMEM_BYTES ((18720 + 6528) * 4)
__global__ void __launch_bounds__(128, 2)
conv2_k(const float* __restrict__ w2, const float* __restrict__ b2) {
    extern __shared__ float sm2[];
    float* ws  = sm2;           // [r(=ci*36+kh*6+kw)][65-padded][co]  8*36*65 = 18720
    float* ins = sm2 + 18720;   // [ci][rr][136]                      8*6*136 = 6528
    const int wt = blockIdx.x, h = blockIdx.y, b = blockIdx.z;
    const int t = threadIdx.x;
    const int cg = t >> 4, wg = t & 15;
    const int w0 = wt * 128;

    float acc[8][8];
#pragma unroll
    for (int i = 0; i < 8; i++)
#pragma unroll
        for (int j = 0; j < 8; j++) acc[i][j] = 0.f;

    for (int ct = 0; ct < 8; ct++) {
        __syncthreads();
        // stage weights (coalesced gmem read, conflict-free scatter via 65-pad)
        for (int j = t; j < 18432; j += 128) {
            int co = j / 288, r = j - co * 288;
            ws[r*65 + co] = w2[co*2304 + ct*288 + r];
        }
        // stage inputs with zero padding
        for (int j = t; j < 6528; j += 128) {
            int ci = j / 816; int r2 = j - ci*816;
            int rr = r2 / 136; int wc = r2 - rr*136;
            int hin = h + rr - 2, winn = w0 - 2 + wc;
            float v = 0.f;
            if (hin >= 0 && hin < H1 && winn >= 0 && winn < W1)
                v = g_h1[((size_t)(b*CH + ct*8 + ci)*H1 + hin)*W1 + winn];
            ins[j] = v;
        }
        __syncthreads();
#pragma unroll
        for (int ci = 0; ci < 8; ci++) {
#pragma unroll
            for (int rr = 0; rr < 6; rr++) {
                const float4* rowp = (const float4*)(ins + (ci*6+rr)*136 + wg*8);
                float4 A = rowp[0], Bv = rowp[1], Cv = rowp[2], Dv = rowp[3];
                float wn[16] = {A.x,A.y,A.z,A.w, Bv.x,Bv.y,Bv.z,Bv.w,
                                Cv.x,Cv.y,Cv.z,Cv.w, Dv.x,Dv.y,Dv.z,Dv.w};
                const float* wp = ws + (ci*36 + rr*6)*65 + cg*8;
#pragma unroll
                for (int kw = 0; kw < 6; kw++) {
#pragma unroll
                    for (int c8 = 0; c8 < 8; c8++) {
                        float wv = wp[kw*65 + c8];
#pragma unroll
                        for (int j = 0; j < 8; j++)
                            acc[c8][j] = fmaf(wv, wn[kw+j], acc[c8][j]);
                    }
                }
            }
        }
    }
    // store with bias + relu
    const int wbase = w0 + wg*8;
#pragma unroll
    for (int c8 = 0; c8 < 8; c8++) {
        int co = cg*8 + c8;
        float bb = b2[co];
        float* op = g_y2 + ((size_t)(b*CH + co)*H1 + h)*W1 + wbase;
        if (wbase + 8 <= W1) {
#pragma unroll
            for (int j = 0; j < 8; j += 2) {
                float2 v;
                v.x = fmaxf(acc[c8][j]   + bb, 0.f);
                v.y = fmaxf(acc[c8][j+1] + bb, 0.f);
                *(float2*)(op + j) = v;
            }
        } else {
#pragma unroll
            for (int j = 0; j < 8; j++)
                if (wbase + j < W1) op[j] = fmaxf(acc[c8][j] + bb, 0.f);
        }
    }
}

// ---------------- conv3: 1x1, 128->64 ch (concat(h1,y2)) ----------
// thread handles 2 spatial positions, out-channels tiled by 32.
__global__ void __launch_bounds__(128)
conv3_k(const float* __restrict__ w3, const float* __restrict__ b3) {
    __shared__ float ws[8192];
    __shared__ float bs[64];
    int t = threadIdx.x;
    for (int j = t; j < 8192; j += 128) ws[j] = w3[j];
    if (t < 64) bs[t] = b3[t];
    __syncthreads();
    int p0 = blockIdx.x*256 + t;
    int p1 = p0 + 128;
    const int TOT = Bsz * HWp;           // 56896
    bool v0 = p0 < TOT, v1 = p1 < TOT;
    int b0 = v0 ? p0 / HWp : 0; int hw0 = v0 ? p0 - b0*HWp : 0;
    int b1i = v1 ? p1 / HWp : 0; int hw1 = v1 ? p1 - b1i*HWp : 0;
    const float* i0h = g_h1 + (size_t)b0*CHWp + hw0;
    const float* i1h = g_h1 + (size_t)b1i*CHWp + hw1;
    const float* i0y = g_y2 + (size_t)b0*CHWp + hw0;
    const float* i1y = g_y2 + (size_t)b1i*CHWp + hw1;

    for (int oc = 0; oc < 2; oc++) {
        float a0[32], a1[32];
#pragma unroll
        for (int k = 0; k < 32; k++) { a0[k] = bs[oc*32+k]; a1[k] = a0[k]; }
#pragma unroll 4
        for (int c = 0; c < 64; c++) {
            float x0 = v0 ? i0h[(size_t)c*HWp] : 0.f;
            float x1 = v1 ? i1h[(size_t)c*HWp] : 0.f;
#pragma unroll
            for (int k = 0; k < 32; k++) {
                float wv = ws[(oc*32+k)*128 + c];
                a0[k] = fmaf(x0, wv, a0[k]);
                a1[k] = fmaf(x1, wv, a1[k]);
            }
        }
#pragma unroll 4
        for (int c = 0; c < 64; c++) {
            float x0 = v0 ? i0y[(size_t)c*HWp] : 0.f;
            float x1 = v1 ? i1y[(size_t)c*HWp] : 0.f;
#pragma unroll
            for (int k = 0; k < 32; k++) {
                float wv = ws[(oc*32+k)*128 + 64 + c];
                a0[k] = fmaf(x0, wv, a0[k]);
                a1[k] = fmaf(x1, wv, a1[k]);
            }
        }
#pragma unroll
        for (int k = 0; k < 32; k++) {
            if (v0) g_h3[(size_t)b0*CHWp + (size_t)(oc*32+k)*HWp + hw0] = a0[k];
            if (v1) g_h3[(size_t)b1i*CHWp + (size_t)(oc*32+k)*HWp + hw1] = a1[k];
        }
    }
}

// ---------------- primary capsules: per-n 8x8 transform -----------
__global__ void pc_k(const float* __restrict__ pw, const float* __restrict__ pb) {
    int n = blockIdx.x*256 + threadIdx.x;
    int b = blockIdx.y;
    if (n >= Ncap) return;
    const float4* uin = (const float4*)(g_h3 + (size_t)b*CHWp + (size_t)n*8);
    float4 q0 = uin[0], q1 = uin[1];
    float ui[8] = {q0.x,q0.y,q0.z,q0.w, q1.x,q1.y,q1.z,q1.w};
    const float4* pbv = (const float4*)(pb + (size_t)n*8);
    float4 r0 = pbv[0], r1 = pbv[1];
    float a[8] = {r0.x,r0.y,r0.z,r0.w, r1.x,r1.y,r1.z,r1.w};
    const float4* pwv = (const float4*)(pw + (size_t)n*64);
#pragma unroll
    for (int i = 0; i < 8; i++) {
        float4 wA = pwv[2*i], wB = pwv[2*i+1];
        a[0] = fmaf(ui[i], wA.x, a[0]); a[1] = fmaf(ui[i], wA.y, a[1]);
        a[2] = fmaf(ui[i], wA.z, a[2]); a[3] = fmaf(ui[i], wA.w, a[3]);
        a[4] = fmaf(ui[i], wB.x, a[4]); a[5] = fmaf(ui[i], wB.y, a[5]);
        a[6] = fmaf(ui[i], wB.z, a[6]); a[7] = fmaf(ui[i], wB.w, a[7]);
    }
    float4* uo = (float4*)(g_u + ((size_t)b*Ncap + n)*8);
    uo[0] = make_float4(a[0],a[1],a[2],a[3]);
    uo[1] = make_float4(a[4],a[5],a[6],a[7]);
}

// ---------------- routing pass (stateless via vsum linearity) -----
// 128 threads = (b:16, e:8). Each block handles a chunk of 64 n's.
// b_log(b,n,e) = u_hat(b,n,e,:) . vsum(b,e,:)  ;  c = softmax_e ;
// s(b,e,o) += c * u_hat(b,n,e,o), accumulated in registers then atomics.
#define RCHUNK 64
__global__ void __launch_bounds__(128)
route_k(const float* __restrict__ ec, int pass) {
    __shared__ float ecs[1024];
    __shared__ float us[128];
    int t = threadIdx.x;
    int b = t >> 3, e = t & 7;
    float* sout = g_s + pass*2048;

    float vs[16];
    const float4* vp = (const float4*)(g_vsum + t*16);
#pragma unroll
    for (int q = 0; q < 4; q++) {
        float4 v = vp[q];
        vs[q*4+0] = v.x; vs[q*4+1] = v.y; vs[q*4+2] = v.z; vs[q*4+3] = v.w;
    }
    float accs[16];
#pragma unroll
    for (int o = 0; o < 16; o++) accs[o] = 0.f;

    int n0 = blockIdx.x * RCHUNK;
    int nEnd = n0 + RCHUNK; if (nEnd > Ncap) nEnd = Ncap;

    for (int n = n0; n < nEnd; n++) {
        __syncthreads();
        const float4* eg = (const float4*)(ec + (size_t)n*1024);
        ((float4*)ecs)[t]       = eg[t];
        ((float4*)ecs)[t + 128] = eg[t + 128];
        us[t] = g_u[((size_t)(t>>3)*Ncap + n)*8 + (t & 7)];
        __syncthreads();

        const float4* up = (const float4*)(us + b*8);
        float4 u0 = up[0], u1 = up[1];
        float ub[8] = {u0.x,u0.y,u0.z,u0.w, u1.x,u1.y,u1.z,u1.w};

        float uh[16];
        float bl = 0.f;
        const float4* ep = (const float4*)(ecs + e*128);
#pragma unroll
        for (int o = 0; o < 16; o++) {
            float4 wA = ep[2*o], wB = ep[2*o+1];
            float s = wA.x*ub[0] + wA.y*ub[1] + wA.z*ub[2] + wA.w*ub[3]
                    + wB.x*ub[4] + wB.y*ub[5] + wB.z*ub[6] + wB.w*ub[7];
            uh[o] = s;
            bl = fmaf(s, vs[o], bl);
        }
        // softmax over e (8-lane groups, aligned within warp)
        float m = bl;
        m = fmaxf(m, __shfl_xor_sync(0xffffffffu, m, 1));
        m = fmaxf(m, __shfl_xor_sync(0xffffffffu, m, 2));
        m = fmaxf(m, __shfl_xor_sync(0xffffffffu, m, 4));
        float ex = __expf(bl - m);
        float den = ex;
        den += __shfl_xor_sync(0xffffffffu, den, 1);
        den += __shfl_xor_sync(0xffffffffu, den, 2);
        den += __shfl_xor_sync(0xffffffffu, den, 4);
        float c = ex / den;
#pragma unroll
        for (int o = 0; o < 16; o++) accs[o] = fmaf(c, uh[o], accs[o]);
    }
#pragma unroll
    for (int o = 0; o < 16; o++) atomicAdd(sout + t*16 + o, accs[o]);
}

// ---------------- squash + accumulate vsum ----------------
__global__ void squash_k(int pass) {
    int t = threadIdx.x; // 128 = (b,e)
    const float* sp = g_s + pass*2048 + t*16;
    float sv[16]; float nn = 0.f;
#pragma unroll
    for (int o = 0; o < 16; o++) { sv[o] = sp[o]; nn = fmaf(sv[o], sv[o], nn); }
    float nrm = sqrtf(nn);
    float sc = nn / (1.f + nn) / (nrm + 1e-8f);
#pragma unroll
    for (int o = 0; o < 16; o++) g_vsum[t*16 + o] += sc * sv[o];
}

__global__ void final_k(float* __restrict__ out) {
    int t = threadIdx.x; // 128
    const float* sp = g_s + 2*2048 + t*16;
    float nn = 0.f;
#pragma unroll
    for (int o = 0; o < 16; o++) { float v = sp[o]; nn = fmaf(v, v, nn); }
    float nrm = sqrtf(nn);
    float sc = nn / (1.f + nn) / (nrm + 1e-8f);
    out[t] = sc * nrm;   // ||squash(s)||
}

// ---------------- launch ----------------
extern "C" void kernel_launch(void* const* d_in, const int* in_sizes, int n_in,
                              void* d_out, int out_size) {
    const float* x  = (const float*)d_in[0];
    const float* w1 = (const float*)d_in[1];
    const float* b1 = (const float*)d_in[2];
    const float* w2 = (const float*)d_in[3];
    const float* b2 = (const float*)d_in[4];
    const float* w3 = (const float*)d_in[5];
    const float* b3 = (const float*)d_in[6];
    const float* pw = (const float*)d_in[7];
    const float* pb = (const float*)d_in[8];
    const float* ec = (const float*)d_in[9];
    float* out = (float*)d_out;

    cudaFuncSetAttribute(conv2_k, cudaFuncAttributeMaxDynamicSharedMemorySize,
                         C2_SMEM_BYTES);

    zero_k<<<24, 256>>>();
    conv1_k<<<dim3(H1, Bsz), 256>>>(x, w1, b1);
    conv2_k<<<dim3(2, H1, Bsz), 128, C2_SMEM_BYTES>>>(w2, b2);
    conv3_k<<<(Bsz*HWp + 255)/256, 128>>>(w3, b3);
    pc_k<<<dim3((Ncap + 255)/256, Bsz), 256>>>(pw, pb);

    int rblocks = (Ncap + RCHUNK - 1) / RCHUNK;
    route_k<<<rblocks, 128>>>(ec, 0);
    squash_k<<<1, 128>>>(0);
    route_k<<<rblocks, 128>>>(ec, 1);
    squash_k<<<1, 128>>>(1);
    route_k<<<rblocks, 128>>>(ec, 2);
    final_k<<<1, 128>>>(out);
}

// round 7
// speedup vs baseline: 2.6415x; 2.6415x over previous
#include <cuda_runtime.h>
#include <cuda_bf16.h>
#include <math.h>

// Shapes
#define Bsz 16
#define CH 64
#define H1 14
#define W1 254
#define HWp (H1*W1)            // 3556
#define CHWp (CH*HWp)          // 227584
#define Ncap 28448
#define Ecls 8
#define ODv 16

// ---------------- scratch ----------------
__device__ float g_h1[Bsz*CHWp];
__device__ float g_y2[Bsz*CHWp];
__device__ float g_h3[Bsz*CHWp];
__device__ float g_u [Bsz*Ncap*8];
__device__ float g_s [3*2048];
__device__ float g_vsum[2048];

__global__ void zero_k() {
    int t = blockIdx.x*256 + threadIdx.x;
    if (t < 3*2048) g_s[t] = 0.f;
    if (t < 2048)   g_vsum[t] = 0.f;
}

// ---------------- conv1: 1->64ch 6x6 stride2, relu ----------------
__global__ void conv1_k(const float* __restrict__ x,
                        const float* __restrict__ w1,
                        const float* __restrict__ b1) {
    __shared__ float xs[6*512];
    __shared__ float ws[2304];
    __shared__ float bs[64];
    int h = blockIdx.x, b = blockIdx.y, t = threadIdx.x;
    const float* xrow = x + b*(32*512) + (2*h)*512;
    for (int j = t; j < 3072; j += 256) xs[j] = xrow[j];
    for (int j = t; j < 2304; j += 256) ws[j] = w1[j];
    if (t < 64) bs[t] = b1[t];
    __syncthreads();
    if (t >= W1) return;
    float win[36];
#pragma unroll
    for (int r = 0; r < 6; r++)
#pragma unroll
        for (int k = 0; k < 6; k++) win[r*6+k] = xs[r*512 + 2*t + k];
    float* outp = g_h1 + (size_t)(b*CH*H1 + h)*W1 + t;
    for (int f = 0; f < 64; f++) {
        float a = bs[f];
        const float* wp = ws + f*36;
#pragma unroll
        for (int k = 0; k < 36; k++) a = fmaf(win[k], wp[k], a);
        outp[(size_t)f*HWp] = fmaxf(a, 0.f);
    }
}

// ---------------- conv2: 64->64ch 6x6 s1 pad(2,3), relu ----------
// 448 blocks (2 wtiles x 14 h x 16 b), 128 thr, 3 blocks/SM -> 1.01 waves.
// cin tiled by 4 through smem (49KB). Thread: 8 couts x 8 w outputs.
#define C2_SMEM_BYTES ((9360 + 3264) * 4)
__global__ void __launch_bounds__(128, 3)
conv2_k(const float* __restrict__ w2, const float* __restrict__ b2) {
    extern __shared__ float sm2[];
    float* ws  = sm2;           // [144 rows][65]  (r = ci*36+kh*6+kw, pad 65)
    float* ins = sm2 + 9360;    // [4 ci][6 rr][136]
    const int wt = blockIdx.x, h = blockIdx.y, b = blockIdx.z;
    const int t = threadIdx.x;
    const int cg = t >> 4, wg = t & 15;
    const int w0 = wt * 128;

    float acc[8][8];
#pragma unroll
    for (int i = 0; i < 8; i++)
#pragma unroll
        for (int j = 0; j < 8; j++) acc[i][j] = 0.f;

    for (int ct = 0; ct < 16; ct++) {
        __syncthreads();
        // weights: 9216 floats, coalesced gmem, conflict-free smem (stride 65)
        for (int j = t; j < 9216; j += 128) {
            int co = j / 144, r = j - co * 144;
            ws[r*65 + co] = w2[co*2304 + ct*144 + r];
        }
        // inputs with zero padding: 3264 floats
        for (int j = t; j < 3264; j += 128) {
            int ci = j / 816; int r2 = j - ci*816;
            int rr = r2 / 136; int wc = r2 - rr*136;
            int hin = h + rr - 2, winn = w0 - 2 + wc;
            float v = 0.f;
            if (hin >= 0 && hin < H1 && (unsigned)winn < (unsigned)W1)
                v = g_h1[((size_t)(b*CH + ct*4 + ci)*H1 + hin)*W1 + winn];
            ins[j] = v;
        }
        __syncthreads();
#pragma unroll
        for (int ci = 0; ci < 4; ci++) {
#pragma unroll
            for (int rr = 0; rr < 6; rr++) {
                const float4* rowp = (const float4*)(ins + (ci*6+rr)*136 + wg*8);
                float4 A = rowp[0], Bv = rowp[1], Cv = rowp[2], Dv = rowp[3];
                float wn[16] = {A.x,A.y,A.z,A.w, Bv.x,Bv.y,Bv.z,Bv.w,
                                Cv.x,Cv.y,Cv.z,Cv.w, Dv.x,Dv.y,Dv.z,Dv.w};
                const float* wp = ws + (ci*36 + rr*6)*65 + cg*8;
#pragma unroll
                for (int kw = 0; kw < 6; kw++) {
#pragma unroll
                    for (int c8 = 0; c8 < 8; c8++) {
                        float wv = wp[kw*65 + c8];
#pragma unroll
                        for (int j = 0; j < 8; j++)
                            acc[c8][j] = fmaf(wv, wn[kw+j], acc[c8][j]);
                    }
                }
            }
        }
    }
    const int wbase = w0 + wg*8;
#pragma unroll
    for (int c8 = 0; c8 < 8; c8++) {
        int co = cg*8 + c8;
        float bb = b2[co];
        float* op = g_y2 + ((size_t)(b*CH + co)*H1 + h)*W1 + wbase;
        if (wbase + 8 <= W1) {
#pragma unroll
            for (int j = 0; j < 8; j += 2) {
                float2 v;
                v.x = fmaxf(acc[c8][j]   + bb, 0.f);
                v.y = fmaxf(acc[c8][j+1] + bb, 0.f);
                *(float2*)(op + j) = v;
            }
        } else {
#pragma unroll
            for (int j = 0; j < 8; j++)
                if (wbase + j < W1) op[j] = fmaxf(acc[c8][j] + bb, 0.f);
        }
    }
}

// ---------------- conv3: 1x1, 128->64 ch ----------
// grid (56 pos-chunks, 4 co-groups), 256 thr; thread = 4 positions x 16 couts.
__global__ void __launch_bounds__(256)
conv3_k(const float* __restrict__ w3, const float* __restrict__ b3) {
    __shared__ float ws[16*128];
    int t = threadIdx.x;
    int co0 = blockIdx.y * 16;
    for (int j = t; j < 2048; j += 256)
        ws[j] = w3[(co0 + (j >> 7))*128 + (j & 127)];
    __syncthreads();
    int p0 = blockIdx.x*1024 + t*4;
    if (p0 >= Bsz*HWp) return;
    int b = p0 / HWp, hw = p0 - b*HWp;
    const float* ih = g_h1 + (size_t)b*CHWp + hw;
    const float* iy = g_y2 + (size_t)b*CHWp + hw;
    float4 acc[16];
#pragma unroll
    for (int k = 0; k < 16; k++) {
        float bb = b3[co0+k];
        acc[k] = make_float4(bb, bb, bb, bb);
    }
#pragma unroll 2
    for (int ci = 0; ci < 64; ci++) {
        float4 xh = *(const float4*)(ih + (size_t)ci*HWp);
        float4 xy = *(const float4*)(iy + (size_t)ci*HWp);
#pragma unroll
        for (int k = 0; k < 16; k++) {
            float wh = ws[k*128 + ci], wy = ws[k*128 + 64 + ci];
            acc[k].x = fmaf(xh.x, wh, acc[k].x);
            acc[k].y = fmaf(xh.y, wh, acc[k].y);
            acc[k].z = fmaf(xh.z, wh, acc[k].z);
            acc[k].w = fmaf(xh.w, wh, acc[k].w);
            acc[k].x = fmaf(xy.x, wy, acc[k].x);
            acc[k].y = fmaf(xy.y, wy, acc[k].y);
            acc[k].z = fmaf(xy.z, wy, acc[k].z);
            acc[k].w = fmaf(xy.w, wy, acc[k].w);
        }
    }
#pragma unroll
    for (int k = 0; k < 16; k++)
        *(float4*)(g_h3 + (size_t)b*CHWp + (size_t)(co0+k)*HWp + hw) = acc[k];
}

// ---------------- primary capsules ----------
__global__ void pc_k(const float* __restrict__ pw, const float* __restrict__ pb) {
    int n = blockIdx.x*256 + threadIdx.x;
    int b = blockIdx.y;
    if (n >= Ncap) return;
    const float4* uin = (const float4*)(g_h3 + (size_t)b*CHWp + (size_t)n*8);
    float4 q0 = uin[0], q1 = uin[1];
    float ui[8] = {q0.x,q0.y,q0.z,q0.w, q1.x,q1.y,q1.z,q1.w};
    const float4* pbv = (const float4*)(pb + (size_t)n*8);
    float4 r0 = pbv[0], r1 = pbv[1];
    float a[8] = {r0.x,r0.y,r0.z,r0.w, r1.x,r1.y,r1.z,r1.w};
    const float4* pwv = (const float4*)(pw + (size_t)n*64);
#pragma unroll
    for (int i = 0; i < 8; i++) {
        float4 wA = pwv[2*i], wB = pwv[2*i+1];
        a[0] = fmaf(ui[i], wA.x, a[0]); a[1] = fmaf(ui[i], wA.y, a[1]);
        a[2] = fmaf(ui[i], wA.z, a[2]); a[3] = fmaf(ui[i], wA.w, a[3]);
        a[4] = fmaf(ui[i], wB.x, a[4]); a[5] = fmaf(ui[i], wB.y, a[5]);
        a[6] = fmaf(ui[i], wB.z, a[6]); a[7] = fmaf(ui[i], wB.w, a[7]);
    }
    float4* uo = (float4*)(g_u + ((size_t)b*Ncap + n)*8);
    uo[0] = make_float4(a[0],a[1],a[2],a[3]);
    uo[1] = make_float4(a[4],a[5],a[6],a[7]);
}

// ---------------- routing pass: cp.async pipelined, conflict-free -----
// 128 threads = (b:16, e:8). GROUP=6 capsules per stage, double-buffered.
// ec rows padded to 132 floats -> e-rows on distinct banks (4-bank shift).
#define RGROUP 6
#define RCHUNK 66
#define ECROW 132
#define ECN (Ecls*ECROW)                // 1056 floats per capsule in smem
#define R_SMEM_BYTES ((2*RGROUP*ECN + 2*RGROUP*128) * 4)   // 56832

__device__ __forceinline__ void cpa16(unsigned d, const void* s) {
    asm volatile("cp.async.cg.shared.global [%0], [%1], 16;" :: "r"(d), "l"(s));
}

__global__ void __launch_bounds__(128)
route_k(const float* __restrict__ ec, int pass) {
    extern __shared__ float rs[];
    float* ecs = rs;                     // [2][RGROUP][ECN]
    float* us  = rs + 2*RGROUP*ECN;      // [2][RGROUP][128]
    int t = threadIdx.x;
    int b = t >> 3, e = t & 7;
    float* sout = g_s + pass*2048;

    float vs[16];
    const float4* vp = (const float4*)(g_vsum + t*16);
#pragma unroll
    for (int q = 0; q < 4; q++) {
        float4 v = vp[q];
        vs[q*4+0] = v.x; vs[q*4+1] = v.y; vs[q*4+2] = v.z; vs[q*4+3] = v.w;
    }
    float accs[16];
#pragma unroll
    for (int o = 0; o < 16; o++) accs[o] = 0.f;

    int n0 = blockIdx.x * RCHUNK;
    int nEnd = n0 + RCHUNK; if (nEnd > Ncap) nEnd = Ncap;
    int gTot = (nEnd - n0 + RGROUP - 1) / RGROUP;

    auto stage = [&](int g, int buf) {
        int nb = n0 + g*RGROUP;
        unsigned ecd = (unsigned)__cvta_generic_to_shared(ecs + buf*RGROUP*ECN);
        unsigned usd = (unsigned)__cvta_generic_to_shared(us  + buf*RGROUP*128);
#pragma unroll
        for (int j = 0; j < 12; j++) {          // RGROUP*256 = 1536 chunks
            int idx = t + j*128;
            int nl = idx >> 8, c = idx & 255;
            int n = nb + nl;
            if (n < nEnd)
                cpa16(ecd + (unsigned)(nl*ECN + (c>>5)*ECROW + (c&31)*4)*4u,
                      ec + (size_t)n*1024 + c*4);
        }
#pragma unroll
        for (int j = 0; j < 2; j++) {           // RGROUP*32 = 192 chunks
            int idx = t + j*128;
            if (idx < RGROUP*32) {
                int nl = idx >> 5, lane = idx & 31;
                int n = nb + nl;
                int bb = lane >> 1, half = lane & 1;
                if (n < nEnd)
                    cpa16(usd + (unsigned)(nl*128 + bb*8 + half*4)*4u,
                          g_u + ((size_t)bb*Ncap + n)*8 + half*4);
            }
        }
        asm volatile("cp.async.commit_group;");
    };

    stage(0, 0);
    for (int g = 0; g < gTot; g++) {
        if (g + 1 < gTot) {
            stage(g+1, (g+1)&1);
            asm volatile("cp.async.wait_group 1;");
        } else {
            asm volatile("cp.async.wait_group 0;");
        }
        __syncthreads();
        int cnt = nEnd - (n0 + g*RGROUP);
        if (cnt > RGROUP) cnt = RGROUP;
        const float* eb = ecs + (g&1)*RGROUP*ECN;
        const float* ub = us  + (g&1)*RGROUP*128;
        for (int nl = 0; nl < cnt; nl++) {
            const float* un = ub + nl*128 + b*8;
            float4 u0 = *(const float4*)un;
            float4 u1 = *(const float4*)(un + 4);
            float ubv[8] = {u0.x,u0.y,u0.z,u0.w, u1.x,u1.y,u1.z,u1.w};
            const float4* ep = (const float4*)(eb + nl*ECN + e*ECROW);
            float uh[16];
            float bl = 0.f;
#pragma unroll
            for (int o = 0; o < 16; o++) {
                float4 wA = ep[2*o], wB = ep[2*o+1];
                float s = wA.x*ubv[0] + wA.y*ubv[1] + wA.z*ubv[2] + wA.w*ubv[3]
                        + wB.x*ubv[4] + wB.y*ubv[5] + wB.z*ubv[6] + wB.w*ubv[7];
                uh[o] = s;
                bl = fmaf(s, vs[o], bl);
            }
            float m = bl;
            m = fmaxf(m, __shfl_xor_sync(0xffffffffu, m, 1));
            m = fmaxf(m, __shfl_xor_sync(0xffffffffu, m, 2));
            m = fmaxf(m, __shfl_xor_sync(0xffffffffu, m, 4));
            float ex = __expf(bl - m);
            float den = ex;
            den += __shfl_xor_sync(0xffffffffu, den, 1);
            den += __shfl_xor_sync(0xffffffffu, den, 2);
            den += __shfl_xor_sync(0xffffffffu, den, 4);
            float c = ex / den;
#pragma unroll
            for (int o = 0; o < 16; o++) accs[o] = fmaf(c, uh[o], accs[o]);
        }
        __syncthreads();
    }
#pragma unroll
    for (int o = 0; o < 16; o++) atomicAdd(sout + t*16 + o, accs[o]);
}

// ---------------- squash + accumulate vsum ----------------
__global__ void squash_k(int pass) {
    int t = threadIdx.x;
    const float* sp = g_s + pass*2048 + t*16;
    float sv[16]; float nn = 0.f;
#pragma unroll
    for (int o = 0; o < 16; o++) { sv[o] = sp[o]; nn = fmaf(sv[o], sv[o], nn); }
    float nrm = sqrtf(nn);
    float sc = nn / (1.f + nn) / (nrm + 1e-8f);
#pragma unroll
    for (int o = 0; o < 16; o++) g_vsum[t*16 + o] += sc * sv[o];
}

__global__ void final_k(float* __restrict__ out) {
    int t = threadIdx.x;
    const float* sp = g_s + 2*2048 + t*16;
    float nn = 0.f;
#pragma unroll
    for (int o = 0; o < 16; o++) { float v = sp[o]; nn = fmaf(v, v, nn); }
    float nrm = sqrtf(nn);
    float sc = nn / (1.f + nn) / (nrm + 1e-8f);
    out[t] = sc * nrm;
}

// ---------------- launch ----------------
extern "C" void kernel_launch(void* const* d_in, const int* in_sizes, int n_in,
                              void* d_out, int out_size) {
    const float* x  = (const float*)d_in[0];
    const float* w1 = (const float*)d_in[1];
    const float* b1 = (const float*)d_in[2];
    const float* w2 = (const float*)d_in[3];
    const float* b2 = (const float*)d_in[4];
    const float* w3 = (const float*)d_in[5];
    const float* b3 = (const float*)d_in[6];
    const float* pw = (const float*)d_in[7];
    const float* pb = (const float*)d_in[8];
    const float* ec = (const float*)d_in[9];
    float* out = (float*)d_out;

    cudaFuncSetAttribute(conv2_k, cudaFuncAttributeMaxDynamicSharedMemorySize,
                         C2_SMEM_BYTES);
    cudaFuncSetAttribute(route_k, cudaFuncAttributeMaxDynamicSharedMemorySize,
                         R_SMEM_BYTES);

    zero_k<<<24, 256>>>();
    conv1_k<<<dim3(H1, Bsz), 256>>>(x, w1, b1);
    conv2_k<<<dim3(2, H1, Bsz), 128, C2_SMEM_BYTES>>>(w2, b2);
    conv3_k<<<dim3(56, 4), 256>>>(w3, b3);
    pc_k<<<dim3((Ncap + 255)/256, Bsz), 256>>>(pw, pb);

    int rblocks = (Ncap + RCHUNK - 1) / RCHUNK;   // 432
    route_k<<<rblocks, 128, R_SMEM_BYTES>>>(ec, 0);
    squash_k<<<1, 128>>>(0);
    route_k<<<rblocks, 128, R_SMEM_BYTES>>>(ec, 1);
    squash_k<<<1, 128>>>(1);
    route_k<<<rblocks, 128, R_SMEM_BYTES>>>(ec, 2);
    final_k<<<1, 128>>>(out);
}

// round 10
// speedup vs baseline: 3.5660x; 1.3500x over previous
#include <cuda_runtime.h>
#include <cuda_bf16.h>
#include <math.h>
#include <stdint.h>

// Shapes
#define Bsz 16
#define CH 64
#define H1 14
#define W1 254
#define HWp (H1*W1)            // 3556
#define CHWp (CH*HWp)          // 227584
#define Ncap 28448
#define Ecls 8
#define ODv 16

// ---------------- scratch ----------------
__device__ float g_h1[Bsz*CHWp];
__device__ float g_y2[Bsz*CHWp];
__device__ float g_h3[Bsz*CHWp];
__device__ float g_u [Bsz*Ncap*8];
__device__ float g_s [3*2048];
__device__ float g_vsum[2048];

__global__ void zero_k() {
    int t = blockIdx.x*256 + threadIdx.x;
    if (t < 3*2048) g_s[t] = 0.f;
    if (t < 2048)   g_vsum[t] = 0.f;
}

// ---------------- conv1: 1->64ch 6x6 stride2, relu ----------------
__global__ void conv1_k(const float* __restrict__ x,
                        const float* __restrict__ w1,
                        const float* __restrict__ b1) {
    __shared__ float xs[6*512];
    __shared__ float ws[2304];
    __shared__ float bs[64];
    int h = blockIdx.x, b = blockIdx.y, t = threadIdx.x;
    const float* xrow = x + b*(32*512) + (2*h)*512;
    for (int j = t; j < 3072; j += 256) xs[j] = xrow[j];
    for (int j = t; j < 2304; j += 256) ws[j] = w1[j];
    if (t < 64) bs[t] = b1[t];
    __syncthreads();
    if (t >= W1) return;
    float win[36];
#pragma unroll
    for (int r = 0; r < 6; r++)
#pragma unroll
        for (int k = 0; k < 6; k++) win[r*6+k] = xs[r*512 + 2*t + k];
    float* outp = g_h1 + (size_t)(b*CH*H1 + h)*W1 + t;
    for (int f = 0; f < 64; f++) {
        float a = bs[f];
        const float* wp = ws + f*36;
#pragma unroll
        for (int k = 0; k < 36; k++) a = fmaf(win[k], wp[k], a);
        outp[(size_t)f*HWp] = fmaxf(a, 0.f);
    }
}

// ============ conv2 via warp-level mma.sync bf16 (3-term split) ============
// Implicit GEMM: D[128 flat positions][64 couts], K = 64ci*36 taps = 2304.
// 16 chunks of K=144 (4 ci). Per chunk: Ah/Al [128][156] bf16, Bh/Bl [64][156].
// 3 HMMA terms per frag: Ah*Bh + Ah*Bl + Al*Bh. fp32 accumulators.
#define LDA 156
#define C2_TOT (Bsz*HWp)          // 56896
#define C2M_SMEM ((2*128*LDA + 2*64*LDA) * 2)   // 119808 bytes

static __device__ __forceinline__ void mma16816(float* c,
    uint32_t a0, uint32_t a1, uint32_t a2, uint32_t a3,
    uint32_t b0, uint32_t b1) {
    asm volatile(
        "mma.sync.aligned.m16n8k16.row.col.f32.bf16.bf16.f32 "
        "{%0,%1,%2,%3}, {%4,%5,%6,%7}, {%8,%9}, {%0,%1,%2,%3};"
        : "+f"(c[0]), "+f"(c[1]), "+f"(c[2]), "+f"(c[3])
        : "r"(a0), "r"(a1), "r"(a2), "r"(a3), "r"(b0), "r"(b1));
}

__global__ void __launch_bounds__(256, 1)
conv2_mma(const float* __restrict__ w2, const float* __restrict__ b2) {
    extern __shared__ __nv_bfloat16 sm[];
    __nv_bfloat16* Ah = sm;
    __nv_bfloat16* Al = Ah + 128*LDA;
    __nv_bfloat16* Bh = Al + 128*LDA;
    __nv_bfloat16* Bl = Bh + 64*LDA;

    const int t = threadIdx.x;
    const int lane = t & 31, wid = t >> 5;
    const int mbase = wid * 16;
    const int pos0 = blockIdx.x * 128;

    float acc[8][4];
#pragma unroll
    for (int nt = 0; nt < 8; nt++)
#pragma unroll
        for (int q = 0; q < 4; q++) acc[nt][q] = 0.f;

    // B staging addressing (constant across chunks)
    const int bco = t >> 2;             // 0..63
    const int bks = (t & 3) * 36;       // 0..108

    for (int cs = 0; cs < 16; cs++) {
        const int ci0 = cs * 4;
        __syncthreads();
        // ---- stage A: 128 pos x 4 ci x 6 kh items, 6 taps each ----
#pragma unroll
        for (int i = 0; i < 12; i++) {
            int idx = t + i*256;              // 0..3071
            int p  = idx & 127;
            int ci = (idx >> 7) & 3;
            int kh = idx >> 9;                // 0..5
            int pos = pos0 + p;
            bool valid = pos < C2_TOT;
            int pc = valid ? pos : 0;
            int b  = pc / HWp;  int hw = pc - b*HWp;
            int h  = hw / W1;   int w  = hw - h*W1;
            int row = h + kh - 2;
            bool vr = valid && row >= 0 && row < H1;
            const float* src = g_h1 + ((size_t)(b*CH + ci0 + ci)*H1 + (vr ? row : 0))*W1;
            int k = ci*36 + kh*6;
            __nv_bfloat16* ah = Ah + p*LDA + k;
            __nv_bfloat16* al = Al + p*LDA + k;
#pragma unroll
            for (int j = 0; j < 6; j++) {
                int c = w - 2 + j;
                float v = (vr && c >= 0 && c < W1) ? __ldg(src + c) : 0.f;
                __nv_bfloat16 hv = __float2bfloat16(v);
                __nv_bfloat16 lv = __float2bfloat16(v - __bfloat162float(hv));
                ah[j] = hv; al[j] = lv;
            }
        }
        // ---- stage B: 64 co x 144 taps (contiguous in w2 per co) ----
        {
            const float* wsrc = w2 + (size_t)bco*2304 + ci0*36 + bks;
            __nv_bfloat16* bh = Bh + bco*LDA + bks;
            __nv_bfloat16* bl = Bl + bco*LDA + bks;
#pragma unroll
            for (int j = 0; j < 36; j++) {
                float v = __ldg(wsrc + j);
                __nv_bfloat16 hv = __float2bfloat16(v);
                __nv_bfloat16 lv = __float2bfloat16(v - __bfloat162float(hv));
                bh[j] = hv; bl[j] = lv;
            }
        }
        __syncthreads();

        // ---- MMA: 9 k16 frags x 8 n-tiles x 3 terms ----
        const int ar = mbase + (lane >> 2);
        const int ac = 2 * (lane & 3);
#pragma unroll
        for (int kf = 0; kf < 9; kf++) {
            int k0 = kf * 16;
            uint32_t ah0 = *(const uint32_t*)(Ah + (ar    )*LDA + k0 + ac);
            uint32_t ah1 = *(const uint32_t*)(Ah + (ar + 8)*LDA + k0 + ac);
            uint32_t ah2 = *(const uint32_t*)(Ah + (ar    )*LDA + k0 + ac + 8);
            uint32_t ah3 = *(const uint32_t*)(Ah + (ar + 8)*LDA + k0 + ac + 8);
            uint32_t al0 = *(const uint32_t*)(Al + (ar    )*LDA + k0 + ac);
            uint32_t al1 = *(const uint32_t*)(Al + (ar + 8)*LDA + k0 + ac);
            uint32_t al2 = *(const uint32_t*)(Al + (ar    )*LDA + k0 + ac + 8);
            uint32_t al3 = *(const uint32_t*)(Al + (ar + 8)*LDA + k0 + ac + 8);
#pragma unroll
            for (int nt = 0; nt < 8; nt++) {
                int n = nt*8 + (lane >> 2);
                uint32_t bh0 = *(const uint32_t*)(Bh + n*LDA + k0 + ac);
                uint32_t bh1 = *(const uint32_t*)(Bh + n*LDA + k0 + ac + 8);
                uint32_t bl0 = *(const uint32_t*)(Bl + n*LDA + k0 + ac);
                uint32_t bl1 = *(const uint32_t*)(Bl + n*LDA + k0 + ac + 8);
                mma16816(acc[nt], ah0, ah1, ah2, ah3, bh0, bh1);
                mma16816(acc[nt], ah0, ah1, ah2, ah3, bl0, bl1);
                mma16816(acc[nt], al0, al1, al2, al3, bh0, bh1);
            }
        }
    }

    // ---- epilogue: bias + relu + scatter store ----
    {
        int p0 = pos0 + mbase + (lane >> 2);
        int p1 = p0 + 8;
        bool v0 = p0 < C2_TOT, v1 = p1 < C2_TOT;
        int pa = v0 ? p0 : 0, pb = v1 ? p1 : 0;
        int b0 = pa / HWp, hw0 = pa - b0*HWp;
        int b1i = pb / HWp, hw1 = pb - b1i*HWp;
        float* o0 = g_y2 + (size_t)b0*CHWp + hw0;
        float* o1 = g_y2 + (size_t)b1i*CHWp + hw1;
#pragma unroll
        for (int nt = 0; nt < 8; nt++) {
            int co = nt*8 + 2*(lane & 3);
            float bb0 = __ldg(b2 + co), bb1 = __ldg(b2 + co + 1);
            if (v0) {
                o0[(size_t)co*HWp]     = fmaxf(acc[nt][0] + bb0, 0.f);
                o0[(size_t)(co+1)*HWp] = fmaxf(acc[nt][1] + bb1, 0.f);
            }
            if (v1) {
                o1[(size_t)co*HWp]     = fmaxf(acc[nt][2] + bb0, 0.f);
                o1[(size_t)(co+1)*HWp] = fmaxf(acc[nt][3] + bb1, 0.f);
            }
        }
    }
}

// ---------------- conv3: 1x1, 128->64 ch ----------
__global__ void __launch_bounds__(256)
conv3_k(const float* __restrict__ w3, const float* __restrict__ b3) {
    __shared__ float ws[16*128];
    int t = threadIdx.x;
    int co0 = blockIdx.y * 16;
    for (int j = t; j < 2048; j += 256)
        ws[j] = w3[(co0 + (j >> 7))*128 + (j & 127)];
    __syncthreads();
    int p0 = blockIdx.x*1024 + t*4;
    if (p0 >= Bsz*HWp) return;
    int b = p0 / HWp, hw = p0 - b*HWp;
    const float* ih = g_h1 + (size_t)b*CHWp + hw;
    const float* iy = g_y2 + (size_t)b*CHWp + hw;
    float4 acc[16];
#pragma unroll
    for (int k = 0; k < 16; k++) {
        float bb = b3[co0+k];
        acc[k] = make_float4(bb, bb, bb, bb);
    }
#pragma unroll 2
    for (int ci = 0; ci < 64; ci++) {
        float4 xh = *(const float4*)(ih + (size_t)ci*HWp);
        float4 xy = *(const float4*)(iy + (size_t)ci*HWp);
#pragma unroll
        for (int k = 0; k < 16; k++) {
            float wh = ws[k*128 + ci], wy = ws[k*128 + 64 + ci];
            acc[k].x = fmaf(xh.x, wh, acc[k].x);
            acc[k].y = fmaf(xh.y, wh, acc[k].y);
            acc[k].z = fmaf(xh.z, wh, acc[k].z);
            acc[k].w = fmaf(xh.w, wh, acc[k].w);
            acc[k].x = fmaf(xy.x, wy, acc[k].x);
            acc[k].y = fmaf(xy.y, wy, acc[k].y);
            acc[k].z = fmaf(xy.z, wy, acc[k].z);
            acc[k].w = fmaf(xy.w, wy, acc[k].w);
        }
    }
#pragma unroll
    for (int k = 0; k < 16; k++)
        *(float4*)(g_h3 + (size_t)b*CHWp + (size_t)(co0+k)*HWp + hw) = acc[k];
}

// ---------------- primary capsules ----------
__global__ void pc_k(const float* __restrict__ pw, const float* __restrict__ pb) {
    int n = blockIdx.x*256 + threadIdx.x;
    int b = blockIdx.y;
    if (n >= Ncap) return;
    const float4* uin = (const float4*)(g_h3 + (size_t)b*CHWp + (size_t)n*8);
    float4 q0 = uin[0], q1 = uin[1];
    float ui[8] = {q0.x,q0.y,q0.z,q0.w, q1.x,q1.y,q1.z,q1.w};
    const float4* pbv = (const float4*)(pb + (size_t)n*8);
    float4 r0 = pbv[0], r1 = pbv[1];
    float a[8] = {r0.x,r0.y,r0.z,r0.w, r1.x,r1.y,r1.z,r1.w};
    const float4* pwv = (const float4*)(pw + (size_t)n*64);
#pragma unroll
    for (int i = 0; i < 8; i++) {
        float4 wA = pwv[2*i], wB = pwv[2*i+1];
        a[0] = fmaf(ui[i], wA.x, a[0]); a[1] = fmaf(ui[i], wA.y, a[1]);
        a[2] = fmaf(ui[i], wA.z, a[2]); a[3] = fmaf(ui[i], wA.w, a[3]);
        a[4] = fmaf(ui[i], wB.x, a[4]); a[5] = fmaf(ui[i], wB.y, a[5]);
        a[6] = fmaf(ui[i], wB.z, a[6]); a[7] = fmaf(ui[i], wB.w, a[7]);
    }
    float4* uo = (float4*)(g_u + ((size_t)b*Ncap + n)*8);
    uo[0] = make_float4(a[0],a[1],a[2],a[3]);
    uo[1] = make_float4(a[4],a[5],a[6],a[7]);
}

// ---------------- routing pass: cp.async pipelined, conflict-free -----
#define RGROUP 6
#define RCHUNK 66
#define ECROW 132
#define ECN (Ecls*ECROW)
#define R_SMEM_BYTES ((2*RGROUP*ECN + 2*RGROUP*128) * 4)

__device__ __forceinline__ void cpa16(unsigned d, const void* s) {
    asm volatile("cp.async.cg.shared.global [%0], [%1], 16;" :: "r"(d), "l"(s));
}

__global__ void __launch_bounds__(128)
route_k(const float* __restrict__ ec, int pass) {
    extern __shared__ float rs[];
    float* ecs = rs;
    float* us  = rs + 2*RGROUP*ECN;
    int t = threadIdx.x;
    int b = t >> 3, e = t & 7;
    float* sout = g_s + pass*2048;

    float vs[16];
    const float4* vp = (const float4*)(g_vsum + t*16);
#pragma unroll
    for (int q = 0; q < 4; q++) {
        float4 v = vp[q];
        vs[q*4+0] = v.x; vs[q*4+1] = v.y; vs[q*4+2] = v.z; vs[q*4+3] = v.w;
    }
    float accs[16];
#pragma unroll
    for (int o = 0; o < 16; o++) accs[o] = 0.f;

    int n0 = blockIdx.x * RCHUNK;
    int nEnd = n0 + RCHUNK; if (nEnd > Ncap) nEnd = Ncap;
    int gTot = (nEnd - n0 + RGROUP - 1) / RGROUP;

    auto stage = [&](int g, int buf) {
        int nb = n0 + g*RGROUP;
        unsigned ecd = (unsigned)__cvta_generic_to_shared(ecs + buf*RGROUP*ECN);
        unsigned usd = (unsigned)__cvta_generic_to_shared(us  + buf*RGROUP*128);
#pragma unroll
        for (int j = 0; j < 12; j++) {
            int idx = t + j*128;
            int nl = idx >> 8, c = idx & 255;
            int n = nb + nl;
            if (n < nEnd)
                cpa16(ecd + (unsigned)(nl*ECN + (c>>5)*ECROW + (c&31)*4)*4u,
                      ec + (size_t)n*1024 + c*4);
        }
#pragma unroll
        for (int j = 0; j < 2; j++) {
            int idx = t + j*128;
            if (idx < RGROUP*32) {
                int nl = idx >> 5, lane = idx & 31;
                int n = nb + nl;
                int bb = lane >> 1, half = lane & 1;
                if (n < nEnd)
                    cpa16(usd + (unsigned)(nl*128 + bb*8 + half*4)*4u,
                          g_u + ((size_t)bb*Ncap + n)*8 + half*4);
            }
        }
        asm volatile("cp.async.commit_group;");
    };

    stage(0, 0);
    for (int g = 0; g < gTot; g++) {
        if (g + 1 < gTot) {
            stage(g+1, (g+1)&1);
            asm volatile("cp.async.wait_group 1;");
        } else {
            asm volatile("cp.async.wait_group 0;");
        }
        __syncthreads();
        int cnt = nEnd - (n0 + g*RGROUP);
        if (cnt > RGROUP) cnt = RGROUP;
        const float* eb = ecs + (g&1)*RGROUP*ECN;
        const float* ub = us  + (g&1)*RGROUP*128;
        for (int nl = 0; nl < cnt; nl++) {
            const float* un = ub + nl*128 + b*8;
            float4 u0 = *(const float4*)un;
            float4 u1 = *(const float4*)(un + 4);
            float ubv[8] = {u0.x,u0.y,u0.z,u0.w, u1.x,u1.y,u1.z,u1.w};
            const float4* ep = (const float4*)(eb + nl*ECN + e*ECROW);
            float uh[16];
            float bl = 0.f;
#pragma unroll
            for (int o = 0; o < 16; o++) {
                float4 wA = ep[2*o], wB = ep[2*o+1];
                float s = wA.x*ubv[0] + wA.y*ubv[1] + wA.z*ubv[2] + wA.w*ubv[3]
                        + wB.x*ubv[4] + wB.y*ubv[5] + wB.z*ubv[6] + wB.w*ubv[7];
                uh[o] = s;
                bl = fmaf(s, vs[o], bl);
            }
            float m = bl;
            m = fmaxf(m, __shfl_xor_sync(0xffffffffu, m, 1));
            m = fmaxf(m, __shfl_xor_sync(0xffffffffu, m, 2));
            m = fmaxf(m, __shfl_xor_sync(0xffffffffu, m, 4));
            float ex = __expf(bl - m);
            float den = ex;
            den += __shfl_xor_sync(0xffffffffu, den, 1);
            den += __shfl_xor_sync(0xffffffffu, den, 2);
            den += __shfl_xor_sync(0xffffffffu, den, 4);
            float c = ex / den;
#pragma unroll
            for (int o = 0; o < 16; o++) accs[o] = fmaf(c, uh[o], accs[o]);
        }
        __syncthreads();
    }
#pragma unroll
    for (int o = 0; o < 16; o++) atomicAdd(sout + t*16 + o, accs[o]);
}

// ---------------- squash + accumulate vsum ----------------
__global__ void squash_k(int pass) {
    int t = threadIdx.x;
    const float* sp = g_s + pass*2048 + t*16;
    float sv[16]; float nn = 0.f;
#pragma unroll
    for (int o = 0; o < 16; o++) { sv[o] = sp[o]; nn = fmaf(sv[o], sv[o], nn); }
    float nrm = sqrtf(nn);
    float sc = nn / (1.f + nn) / (nrm + 1e-8f);
#pragma unroll
    for (int o = 0; o < 16; o++) g_vsum[t*16 + o] += sc * sv[o];
}

__global__ void final_k(float* __restrict__ out) {
    int t = threadIdx.x;
    const float* sp = g_s + 2*2048 + t*16;
    float nn = 0.f;
#pragma unroll
    for (int o = 0; o < 16; o++) { float v = sp[o]; nn = fmaf(v, v, nn); }
    float nrm = sqrtf(nn);
    float sc = nn / (1.f + nn) / (nrm + 1e-8f);
    out[t] = sc * nrm;
}

// ---------------- launch ----------------
extern "C" void kernel_launch(void* const* d_in, const int* in_sizes, int n_in,
                              void* d_out, int out_size) {
    const float* x  = (const float*)d_in[0];
    const float* w1 = (const float*)d_in[1];
    const float* b1 = (const float*)d_in[2];
    const float* w2 = (const float*)d_in[3];
    const float* b2 = (const float*)d_in[4];
    const float* w3 = (const float*)d_in[5];
    const float* b3 = (const float*)d_in[6];
    const float* pw = (const float*)d_in[7];
    const float* pb = (const float*)d_in[8];
    const float* ec = (const float*)d_in[9];
    float* out = (float*)d_out;

    cudaFuncSetAttribute(conv2_mma, cudaFuncAttributeMaxDynamicSharedMemorySize,
                         C2M_SMEM);
    cudaFuncSetAttribute(route_k, cudaFuncAttributeMaxDynamicSharedMemorySize,
                         R_SMEM_BYTES);

    zero_k<<<24, 256>>>();
    conv1_k<<<dim3(H1, Bsz), 256>>>(x, w1, b1);
    int c2blocks = (C2_TOT + 127) / 128;          // 445
    conv2_mma<<<c2blocks, 256, C2M_SMEM>>>(w2, b2);
    conv3_k<<<dim3(56, 4), 256>>>(w3, b3);
    pc_k<<<dim3((Ncap + 255)/256, Bsz), 256>>>(pw, pb);

    int rblocks = (Ncap + RCHUNK - 1) / RCHUNK;
    route_k<<<rblocks, 128, R_SMEM_BYTES>>>(ec, 0);
    squash_k<<<1, 128>>>(0);
    route_k<<<rblocks, 128, R_SMEM_BYTES>>>(ec, 1);
    squash_k<<<1, 128>>>(1);
    route_k<<<rblocks, 128, R_SMEM_BYTES>>>(ec, 2);
    final_k<<<1, 128>>>(out);
}

// round 11
// speedup vs baseline: 4.4305x; 1.2424x over previous
#include <cuda_runtime.h>
#include <cuda_bf16.h>
#include <math.h>
#include <stdint.h>

// Shapes
#define Bsz 16
#define CH 64
#define H1 14
#define W1 254
#define HWp (H1*W1)            // 3556
#define CHWp (CH*HWp)          // 227584
#define Ncap 28448
#define Ecls 8
#define ODv 16

// ---------------- scratch ----------------
__device__ float g_h1[Bsz*CHWp];
__device__ float g_y2[Bsz*CHWp];
__device__ float g_h3[Bsz*CHWp];
__device__ float g_u [Bsz*Ncap*8];
__device__ float g_s [3*2048];
__device__ float g_vsum[2048];
__device__ __nv_bfloat16 g_w2h[64*2304];
__device__ __nv_bfloat16 g_w2l[64*2304];

__global__ void zero_k() {
    int t = blockIdx.x*256 + threadIdx.x;
    if (t < 3*2048) g_s[t] = 0.f;
    if (t < 2048)   g_vsum[t] = 0.f;
}

// ---------------- prep: split w2 into bf16 hi/lo ----------------
__global__ void splitw2_k(const float* __restrict__ w2) {
    int i = blockIdx.x*256 + threadIdx.x;
    if (i < 64*2304) {
        float v = w2[i];
        __nv_bfloat16 h = __float2bfloat16(v);
        g_w2h[i] = h;
        g_w2l[i] = __float2bfloat16(v - __bfloat162float(h));
    }
}

// ---------------- conv1: 1->64ch 6x6 stride2, relu ----------------
__global__ void conv1_k(const float* __restrict__ x,
                        const float* __restrict__ w1,
                        const float* __restrict__ b1) {
    __shared__ float xs[6*512];
    __shared__ float ws[2304];
    __shared__ float bs[64];
    int h = blockIdx.x, b = blockIdx.y, t = threadIdx.x;
    const float* xrow = x + b*(32*512) + (2*h)*512;
    for (int j = t; j < 3072; j += 256) xs[j] = xrow[j];
    for (int j = t; j < 2304; j += 256) ws[j] = w1[j];
    if (t < 64) bs[t] = b1[t];
    __syncthreads();
    if (t >= W1) return;
    float win[36];
#pragma unroll
    for (int r = 0; r < 6; r++)
#pragma unroll
        for (int k = 0; k < 6; k++) win[r*6+k] = xs[r*512 + 2*t + k];
    float* outp = g_h1 + (size_t)(b*CH*H1 + h)*W1 + t;
    for (int f = 0; f < 64; f++) {
        float a = bs[f];
        const float* wp = ws + f*36;
#pragma unroll
        for (int k = 0; k < 36; k++) a = fmaf(win[k], wp[k], a);
        outp[(size_t)f*HWp] = fmaxf(a, 0.f);
    }
}

// ============ conv2 via mma.sync bf16 (3-term), cp.async B, raw+expand A ====
// Grid (2 wtiles, 14 h, 16 b). M = 128 w-positions, N = 64 couts,
// K chunks of 144 (4 ci x 36 taps), 16 chunks.
#define LDA 156
#define LDB 168
#define RAW_FLOATS 3264                 // 4ci x 6kh x 136 cols
#define A_ELEMS (128*LDA)               // 19968 per (hi|lo)
#define B_ELEMS (64*LDB)                // 10752 per (hi|lo)
#define C2_SMEM (RAW_FLOATS*4 + 2*A_ELEMS*2 + 4*B_ELEMS*2)   // 178944 B

static __device__ __forceinline__ void mma16816(float* c,
    uint32_t a0, uint32_t a1, uint32_t a2, uint32_t a3,
    uint32_t b0, uint32_t b1) {
    asm volatile(
        "mma.sync.aligned.m16n8k16.row.col.f32.bf16.bf16.f32 "
        "{%0,%1,%2,%3}, {%4,%5,%6,%7}, {%8,%9}, {%0,%1,%2,%3};"
        : "+f"(c[0]), "+f"(c[1]), "+f"(c[2]), "+f"(c[3])
        : "r"(a0), "r"(a1), "r"(a2), "r"(a3), "r"(b0), "r"(b1));
}
__device__ __forceinline__ void cpa16g(unsigned d, const void* s) {
    asm volatile("cp.async.cg.shared.global [%0], [%1], 16;" :: "r"(d), "l"(s));
}

__global__ void __launch_bounds__(256, 1)
conv2_mma(const float* __restrict__ b2) {
    extern __shared__ char cs2[];
    float* raw = (float*)cs2;                                // [4][6][136]
    __nv_bfloat16* Ah = (__nv_bfloat16*)(cs2 + RAW_FLOATS*4);
    __nv_bfloat16* Al = Ah + A_ELEMS;
    __nv_bfloat16* Bb = Al + A_ELEMS;    // [buf2][hl2][64][LDB]

    const int wt = blockIdx.x, h = blockIdx.y, b = blockIdx.z;
    const int t = threadIdx.x, lane = t & 31, wid = t >> 5;
    const int mbase = wid * 16;
    const int w0 = wt * 128;
    const unsigned bB = (unsigned)__cvta_generic_to_shared(Bb);

    float acc[8][4];
#pragma unroll
    for (int nt = 0; nt < 8; nt++)
#pragma unroll
        for (int q = 0; q < 4; q++) acc[nt][q] = 0.f;

    auto stageB = [&](int chunk, int buf) {
#pragma unroll
        for (int i = 0; i < 9; i++) {
            int idx = t + i*256;                 // 0..2303
            int hl = idx >= 1152 ? 1 : 0;
            int r = idx - hl*1152;
            int co = r / 18, j = r - co*18;
            const __nv_bfloat16* src = (hl ? g_w2l : g_w2h)
                + (size_t)co*2304 + chunk*144;
            cpa16g(bB + (unsigned)((buf*2 + hl)*B_ELEMS + co*LDB)*2 + j*16,
                   (const char*)src + j*16);
        }
        asm volatile("cp.async.commit_group;");
    };

    stageB(0, 0);

    for (int chunk = 0; chunk < 16; chunk++) {
        const int ci0 = chunk * 4;
        const int buf = chunk & 1;
        __syncthreads();    // prior mma done -> raw/A reusable
        // ---- stage raw input rows (fp32, guarded) ----
        for (int j = t; j < RAW_FLOATS; j += 256) {
            int ci = j / 816; int r2 = j - ci*816;
            int rr = r2 / 136; int wc = r2 - rr*136;
            int hin = h + rr - 2, winn = w0 - 2 + wc;
            float v = 0.f;
            if (hin >= 0 && hin < H1 && (unsigned)winn < (unsigned)W1)
                v = g_h1[((size_t)(b*CH + ci0 + ci)*H1 + hin)*W1 + winn];
            raw[j] = v;
        }
        __syncthreads();
        // ---- expand raw -> A hi/lo tiles ----
#pragma unroll
        for (int i = 0; i < 12; i++) {
            int idx = t + i*256;            // 3072 = 128p x 4ci x 6kh
            int p  = idx & 127;
            int ci = (idx >> 7) & 3;
            int kh = idx >> 9;
            const float* rp = raw + ci*816 + kh*136 + p;
            float v0 = rp[0], v1 = rp[1], v2 = rp[2];
            float v3 = rp[3], v4 = rp[4], v5 = rp[5];
            __nv_bfloat162 h0 = __floats2bfloat162_rn(v0, v1);
            __nv_bfloat162 h1v = __floats2bfloat162_rn(v2, v3);
            __nv_bfloat162 h2 = __floats2bfloat162_rn(v4, v5);
            __nv_bfloat162 l0 = __floats2bfloat162_rn(
                v0 - __bfloat162float(h0.x), v1 - __bfloat162float(h0.y));
            __nv_bfloat162 l1 = __floats2bfloat162_rn(
                v2 - __bfloat162float(h1v.x), v3 - __bfloat162float(h1v.y));
            __nv_bfloat162 l2 = __floats2bfloat162_rn(
                v4 - __bfloat162float(h2.x), v5 - __bfloat162float(h2.y));
            int k = ci*36 + kh*6;
            uint32_t* ah = (uint32_t*)(Ah + p*LDA + k);
            uint32_t* al = (uint32_t*)(Al + p*LDA + k);
            ah[0] = *(uint32_t*)&h0; ah[1] = *(uint32_t*)&h1v; ah[2] = *(uint32_t*)&h2;
            al[0] = *(uint32_t*)&l0; al[1] = *(uint32_t*)&l1; al[2] = *(uint32_t*)&l2;
        }
        // ---- prefetch next B, wait for current B ----
        if (chunk < 15) {
            stageB(chunk + 1, buf ^ 1);
            asm volatile("cp.async.wait_group 1;");
        } else {
            asm volatile("cp.async.wait_group 0;");
        }
        __syncthreads();

        const __nv_bfloat16* Bh = Bb + (buf*2 + 0)*B_ELEMS;
        const __nv_bfloat16* Bl = Bb + (buf*2 + 1)*B_ELEMS;
        const int ar = mbase + (lane >> 2);
        const int ac = 2 * (lane & 3);
#pragma unroll
        for (int kf = 0; kf < 9; kf++) {
            int k0 = kf * 16;
            uint32_t ah0 = *(const uint32_t*)(Ah + (ar    )*LDA + k0 + ac);
            uint32_t ah1 = *(const uint32_t*)(Ah + (ar + 8)*LDA + k0 + ac);
            uint32_t ah2 = *(const uint32_t*)(Ah + (ar    )*LDA + k0 + ac + 8);
            uint32_t ah3 = *(const uint32_t*)(Ah + (ar + 8)*LDA + k0 + ac + 8);
            uint32_t al0 = *(const uint32_t*)(Al + (ar    )*LDA + k0 + ac);
            uint32_t al1 = *(const uint32_t*)(Al + (ar + 8)*LDA + k0 + ac);
            uint32_t al2 = *(const uint32_t*)(Al + (ar    )*LDA + k0 + ac + 8);
            uint32_t al3 = *(const uint32_t*)(Al + (ar + 8)*LDA + k0 + ac + 8);
#pragma unroll
            for (int nt = 0; nt < 8; nt++) {
                int n = nt*8 + (lane >> 2);
                uint32_t bh0 = *(const uint32_t*)(Bh + n*LDB + k0 + ac);
                uint32_t bh1 = *(const uint32_t*)(Bh + n*LDB + k0 + ac + 8);
                uint32_t bl0 = *(const uint32_t*)(Bl + n*LDB + k0 + ac);
                uint32_t bl1 = *(const uint32_t*)(Bl + n*LDB + k0 + ac + 8);
                mma16816(acc[nt], ah0, ah1, ah2, ah3, bh0, bh1);
                mma16816(acc[nt], ah0, ah1, ah2, ah3, bl0, bl1);
                mma16816(acc[nt], al0, al1, al2, al3, bh0, bh1);
            }
        }
    }

    // ---- epilogue: bias + relu + store ----
    {
        int p0 = mbase + (lane >> 2);
        int p1 = p0 + 8;
        int wA = w0 + p0, wBp = w0 + p1;
        bool v0 = wA < W1, v1 = wBp < W1;
        float* orow = g_y2 + ((size_t)(b*CH)*H1 + h)*W1;
#pragma unroll
        for (int nt = 0; nt < 8; nt++) {
            int co = nt*8 + 2*(lane & 3);
            float bb0 = __ldg(b2 + co), bb1 = __ldg(b2 + co + 1);
            if (v0) {
                orow[(size_t)co*HWp + wA]     = fmaxf(acc[nt][0] + bb0, 0.f);
                orow[(size_t)(co+1)*HWp + wA] = fmaxf(acc[nt][1] + bb1, 0.f);
            }
            if (v1) {
                orow[(size_t)co*HWp + wBp]     = fmaxf(acc[nt][2] + bb0, 0.f);
                orow[(size_t)(co+1)*HWp + wBp] = fmaxf(acc[nt][3] + bb1, 0.f);
            }
        }
    }
}

// ---------------- conv3: 1x1, 128->64 ch, 32-cout groups ----------
__global__ void __launch_bounds__(256)
conv3_k(const float* __restrict__ w3, const float* __restrict__ b3) {
    __shared__ float ws[32*128];
    int t = threadIdx.x;
    int co0 = blockIdx.y * 32;
    for (int j = t; j < 4096; j += 256)
        ws[j] = w3[(co0 + (j >> 7))*128 + (j & 127)];
    __syncthreads();
    int p0 = blockIdx.x*1024 + t*4;
    if (p0 >= Bsz*HWp) return;
    int b = p0 / HWp, hw = p0 - b*HWp;
    const float* ih = g_h1 + (size_t)b*CHWp + hw;
    const float* iy = g_y2 + (size_t)b*CHWp + hw;
    float4 acc[32];
#pragma unroll
    for (int k = 0; k < 32; k++) {
        float bb = b3[co0+k];
        acc[k] = make_float4(bb, bb, bb, bb);
    }
#pragma unroll 2
    for (int ci = 0; ci < 64; ci++) {
        float4 xh = *(const float4*)(ih + (size_t)ci*HWp);
        float4 xy = *(const float4*)(iy + (size_t)ci*HWp);
#pragma unroll
        for (int k = 0; k < 32; k++) {
            float wh = ws[k*128 + ci], wy = ws[k*128 + 64 + ci];
            acc[k].x = fmaf(xh.x, wh, acc[k].x);
            acc[k].y = fmaf(xh.y, wh, acc[k].y);
            acc[k].z = fmaf(xh.z, wh, acc[k].z);
            acc[k].w = fmaf(xh.w, wh, acc[k].w);
            acc[k].x = fmaf(xy.x, wy, acc[k].x);
            acc[k].y = fmaf(xy.y, wy, acc[k].y);
            acc[k].z = fmaf(xy.z, wy, acc[k].z);
            acc[k].w = fmaf(xy.w, wy, acc[k].w);
        }
    }
#pragma unroll
    for (int k = 0; k < 32; k++)
        *(float4*)(g_h3 + (size_t)b*CHWp + (size_t)(co0+k)*HWp + hw) = acc[k];
}

// ---------------- primary capsules ----------
__global__ void pc_k(const float* __restrict__ pw, const float* __restrict__ pb) {
    int n = blockIdx.x*256 + threadIdx.x;
    int b = blockIdx.y;
    if (n >= Ncap) return;
    const float4* uin = (const float4*)(g_h3 + (size_t)b*CHWp + (size_t)n*8);
    float4 q0 = uin[0], q1 = uin[1];
    float ui[8] = {q0.x,q0.y,q0.z,q0.w, q1.x,q1.y,q1.z,q1.w};
    const float4* pbv = (const float4*)(pb + (size_t)n*8);
    float4 r0 = pbv[0], r1 = pbv[1];
    float a[8] = {r0.x,r0.y,r0.z,r0.w, r1.x,r1.y,r1.z,r1.w};
    const float4* pwv = (const float4*)(pw + (size_t)n*64);
#pragma unroll
    for (int i = 0; i < 8; i++) {
        float4 wA = pwv[2*i], wB = pwv[2*i+1];
        a[0] = fmaf(ui[i], wA.x, a[0]); a[1] = fmaf(ui[i], wA.y, a[1]);
        a[2] = fmaf(ui[i], wA.z, a[2]); a[3] = fmaf(ui[i], wA.w, a[3]);
        a[4] = fmaf(ui[i], wB.x, a[4]); a[5] = fmaf(ui[i], wB.y, a[5]);
        a[6] = fmaf(ui[i], wB.z, a[6]); a[7] = fmaf(ui[i], wB.w, a[7]);
    }
    float4* uo = (float4*)(g_u + ((size_t)b*Ncap + n)*8);
    uo[0] = make_float4(a[0],a[1],a[2],a[3]);
    uo[1] = make_float4(a[4],a[5],a[6],a[7]);
}

// ---------------- routing pass: cp.async pipelined, conflict-free -----
#define RGROUP 6
#define RCHUNK 66
#define ECROW 132
#define ECN (Ecls*ECROW)
#define R_SMEM_BYTES ((2*RGROUP*ECN + 2*RGROUP*128) * 4)

__device__ __forceinline__ void cpa16(unsigned d, const void* s) {
    asm volatile("cp.async.cg.shared.global [%0], [%1], 16;" :: "r"(d), "l"(s));
}

__global__ void __launch_bounds__(128)
route_k(const float* __restrict__ ec, int pass) {
    extern __shared__ float rs[];
    float* ecs = rs;
    float* us  = rs + 2*RGROUP*ECN;
    int t = threadIdx.x;
    int b = t >> 3, e = t & 7;
    float* sout = g_s + pass*2048;

    float vs[16];
    const float4* vp = (const float4*)(g_vsum + t*16);
#pragma unroll
    for (int q = 0; q < 4; q++) {
        float4 v = vp[q];
        vs[q*4+0] = v.x; vs[q*4+1] = v.y; vs[q*4+2] = v.z; vs[q*4+3] = v.w;
    }
    float accs[16];
#pragma unroll
    for (int o = 0; o < 16; o++) accs[o] = 0.f;

    int n0 = blockIdx.x * RCHUNK;
    int nEnd = n0 + RCHUNK; if (nEnd > Ncap) nEnd = Ncap;
    int gTot = (nEnd - n0 + RGROUP - 1) / RGROUP;

    auto stage = [&](int g, int buf) {
        int nb = n0 + g*RGROUP;
        unsigned ecd = (unsigned)__cvta_generic_to_shared(ecs + buf*RGROUP*ECN);
        unsigned usd = (unsigned)__cvta_generic_to_shared(us  + buf*RGROUP*128);
#pragma unroll
        for (int j = 0; j < 12; j++) {
            int idx = t + j*128;
            int nl = idx >> 8, c = idx & 255;
            int n = nb + nl;
            if (n < nEnd)
                cpa16(ecd + (unsigned)(nl*ECN + (c>>5)*ECROW + (c&31)*4)*4u,
                      ec + (size_t)n*1024 + c*4);
        }
#pragma unroll
        for (int j = 0; j < 2; j++) {
            int idx = t + j*128;
            if (idx < RGROUP*32) {
                int nl = idx >> 5, lane = idx & 31;
                int n = nb + nl;
                int bb = lane >> 1, half = lane & 1;
                if (n < nEnd)
                    cpa16(usd + (unsigned)(nl*128 + bb*8 + half*4)*4u,
                          g_u + ((size_t)bb*Ncap + n)*8 + half*4);
            }
        }
        asm volatile("cp.async.commit_group;");
    };

    stage(0, 0);
    for (int g = 0; g < gTot; g++) {
        if (g + 1 < gTot) {
            stage(g+1, (g+1)&1);
            asm volatile("cp.async.wait_group 1;");
        } else {
            asm volatile("cp.async.wait_group 0;");
        }
        __syncthreads();
        int cnt = nEnd - (n0 + g*RGROUP);
        if (cnt > RGROUP) cnt = RGROUP;
        const float* eb = ecs + (g&1)*RGROUP*ECN;
        const float* ub = us  + (g&1)*RGROUP*128;
        for (int nl = 0; nl < cnt; nl++) {
            const float* un = ub + nl*128 + b*8;
            float4 u0 = *(const float4*)un;
            float4 u1 = *(const float4*)(un + 4);
            float ubv[8] = {u0.x,u0.y,u0.z,u0.w, u1.x,u1.y,u1.z,u1.w};
            const float4* ep = (const float4*)(eb + nl*ECN + e*ECROW);
            float uh[16];
            float bl = 0.f;
#pragma unroll
            for (int o = 0; o < 16; o++) {
                float4 wA = ep[2*o], wB = ep[2*o+1];
                float s = wA.x*ubv[0] + wA.y*ubv[1] + wA.z*ubv[2] + wA.w*ubv[3]
                        + wB.x*ubv[4] + wB.y*ubv[5] + wB.z*ubv[6] + wB.w*ubv[7];
                uh[o] = s;
                bl = fmaf(s, vs[o], bl);
            }
            float m = bl;
            m = fmaxf(m, __shfl_xor_sync(0xffffffffu, m, 1));
            m = fmaxf(m, __shfl_xor_sync(0xffffffffu, m, 2));
            m = fmaxf(m, __shfl_xor_sync(0xffffffffu, m, 4));
            float ex = __expf(bl - m);
            float den = ex;
            den += __shfl_xor_sync(0xffffffffu, den, 1);
            den += __shfl_xor_sync(0xffffffffu, den, 2);
            den += __shfl_xor_sync(0xffffffffu, den, 4);
            float c = ex / den;
#pragma unroll
            for (int o = 0; o < 16; o++) accs[o] = fmaf(c, uh[o], accs[o]);
        }
        __syncthreads();
    }
#pragma unroll
    for (int o = 0; o < 16; o++) atomicAdd(sout + t*16 + o, accs[o]);
}

// ---------------- squash + accumulate vsum ----------------
__global__ void squash_k(int pass) {
    int t = threadIdx.x;
    const float* sp = g_s + pass*2048 + t*16;
    float sv[16]; float nn = 0.f;
#pragma unroll
    for (int o = 0; o < 16; o++) { sv[o] = sp[o]; nn = fmaf(sv[o], sv[o], nn); }
    float nrm = sqrtf(nn);
    float sc = nn / (1.f + nn) / (nrm + 1e-8f);
#pragma unroll
    for (int o = 0; o < 16; o++) g_vsum[t*16 + o] += sc * sv[o];
}

__global__ void final_k(float* __restrict__ out) {
    int t = threadIdx.x;
    const float* sp = g_s + 2*2048 + t*16;
    float nn = 0.f;
#pragma unroll
    for (int o = 0; o < 16; o++) { float v = sp[o]; nn = fmaf(v, v, nn); }
    float nrm = sqrtf(nn);
    float sc = nn / (1.f + nn) / (nrm + 1e-8f);
    out[t] = sc * nrm;
}

// ---------------- launch ----------------
extern "C" void kernel_launch(void* const* d_in, const int* in_sizes, int n_in,
                              void* d_out, int out_size) {
    const float* x  = (const float*)d_in[0];
    const float* w1 = (const float*)d_in[1];
    const float* b1 = (const float*)d_in[2];
    const float* w2 = (const float*)d_in[3];
    const float* b2 = (const float*)d_in[4];
    const float* w3 = (const float*)d_in[5];
    const float* b3 = (const float*)d_in[6];
    const float* pw = (const float*)d_in[7];
    const float* pb = (const float*)d_in[8];
    const float* ec = (const float*)d_in[9];
    float* out = (float*)d_out;

    cudaFuncSetAttribute(conv2_mma, cudaFuncAttributeMaxDynamicSharedMemorySize,
                         C2_SMEM);
    cudaFuncSetAttribute(route_k, cudaFuncAttributeMaxDynamicSharedMemorySize,
                         R_SMEM_BYTES);

    zero_k<<<24, 256>>>();
    splitw2_k<<<(64*2304 + 255)/256, 256>>>(w2);
    conv1_k<<<dim3(H1, Bsz), 256>>>(x, w1, b1);
    conv2_mma<<<dim3(2, H1, Bsz), 256, C2_SMEM>>>(b2);
    conv3_k<<<dim3(56, 2), 256>>>(w3, b3);
    pc_k<<<dim3((Ncap + 255)/256, Bsz), 256>>>(pw, pb);

    int rblocks = (Ncap + RCHUNK - 1) / RCHUNK;
    route_k<<<rblocks, 128, R_SMEM_BYTES>>>(ec, 0);
    squash_k<<<1, 128>>>(0);
    route_k<<<rblocks, 128, R_SMEM_BYTES>>>(ec, 1);
    squash_k<<<1, 128>>>(1);
    route_k<<<rblocks, 128, R_SMEM_BYTES>>>(ec, 2);
    final_k<<<1, 128>>>(out);
}